// round 10
// baseline (speedup 1.0000x reference)
#include <cuda_runtime.h>
#include <math.h>

#define NT1 1024

typedef unsigned long long u64;

// Scratch (static device arrays — no allocation)
__device__ u64   g_state[32u * 65536u];   // 16 MB: [b][k][b0][b15][idx14], packed (re,im)
__device__ float g_featsP[4 * 16 * 24];   // partial quantum features [part][b][24]

// ---------------- f32x2 packed helpers (sm_103a) ----------------
__device__ __forceinline__ u64 pk2(float x, float y) {
    u64 r; asm("mov.b64 %0, {%1,%2};" : "=l"(r) : "f"(x), "f"(y)); return r;
}
__device__ __forceinline__ u64 f2mul(u64 a, u64 b) {
    u64 d; asm("mul.rn.f32x2 %0, %1, %2;" : "=l"(d) : "l"(a), "l"(b)); return d;
}
__device__ __forceinline__ u64 f2fma(u64 a, u64 b, u64 c) {
    u64 d; asm("fma.rn.f32x2 %0, %1, %2, %3;" : "=l"(d) : "l"(a), "l"(b), "l"(c)); return d;
}
__device__ __forceinline__ u64 f2swap(u64 a) {
    unsigned lo, hi; asm("mov.b64 {%0,%1}, %2;" : "=r"(lo), "=r"(hi) : "l"(a));
    u64 d; asm("mov.b64 %0, {%1,%2};" : "=l"(d) : "r"(hi), "r"(lo)); return d;
}
__device__ __forceinline__ void upk(u64 a, float& x, float& y) {
    asm("mov.b64 {%0,%1}, %2;" : "=f"(x), "=f"(y) : "l"(a));
}

// Swizzle chosen so the bank map (phys & 15) is injective on every
// iteration's 4-bit lane subspace: idx0->b0, idx1->b1, idx2->b2, idx3->b3,
// idx4->b2, idx5->b3, idx6->b0+b2, idx7->b1+b3.
__device__ __forceinline__ int sphys(int idx) {
    return idx ^ ((idx >> 2) & 12) ^ (5 * ((idx >> 6) & 3));
}

// RY on packed pair: u' = c*u - s*v ; v' = s*u + c*v (elementwise on re/im)
template<int T, int N>
__device__ __forceinline__ void ryg(u64* a, u64 cc, u64 ss, u64 nss) {
#pragma unroll
    for (int m = 0; m < N; m++) {
        if (m & (1 << T)) continue;
        int v = m | (1 << T);
        u64 au = a[m], av = a[v];
        a[m] = f2fma(cc, au, f2mul(nss, av));
        a[v] = f2fma(cc, av, f2mul(ss, au));
    }
}
// RX: u' = c*u + (s,-s)*swap(v) ; v' = c*v + (s,-s)*swap(u)
template<int T, int N>
__device__ __forceinline__ void rxg(u64* a, u64 cc, u64 sp) {
#pragma unroll
    for (int m = 0; m < N; m++) {
        if (m & (1 << T)) continue;
        int v = m | (1 << T);
        u64 au = a[m], av = a[v];
        a[m] = f2fma(cc, au, f2mul(sp, f2swap(av)));
        a[v] = f2fma(cc, av, f2mul(sp, f2swap(au)));
    }
}
template<int C, int T, int N>
__device__ __forceinline__ void cng(u64* a) {
#pragma unroll
    for (int m = 0; m < N; m++) {
        if (!(m & (1 << C)) || (m & (1 << T))) continue;
        int v = m | (1 << T);
        u64 t = a[m]; a[m] = a[v]; a[v] = t;
    }
}

// ---------------- compile-time parity masks for the 36-CNOT cascade ----------------
// inner: e5 bits (bit4=wire11 .. bit0=wire15); outer: idx14 bits 13..4 (wires 1..10)
struct Masks { unsigned inner[12]; unsigned outer14[12]; unsigned w0f[12]; };
__host__ __device__ constexpr Masks compute_masks() {
    Masks M{};
    int cs[36] = {}, ts2[36] = {}; int n = 0;
    for (int i = 0; i < 12; i++) {
        cs[n] = i + 1; ts2[n] = i; n++;
        cs[n] = i + 3; ts2[n] = i; n++;
        cs[n] = i + 4; ts2[n] = i; n++;
    }
    for (int w = 0; w < 12; w++) {
        unsigned m = 1u << w;
        for (int j = 35; j >= 0; --j)
            if ((m >> ts2[j]) & 1u) m ^= 1u << cs[j];
        unsigned inner = 0, outer = 0;
        M.w0f[w] = m & 1u;
        for (int ww = 1; ww <= 10; ++ww)
            if ((m >> ww) & 1u) outer |= 1u << (14 - ww);
        for (int ww = 11; ww <= 15; ++ww)
            if ((m >> ww) & 1u) inner |= 1u << (15 - ww);
        M.inner[w] = inner; M.outer14[w] = outer;
    }
    return M;
}

// ---------------- kernel 1: 14-qubit smem-resident simulation ----------------
// 128 blocks: bi = ((b*2 + k)*2 + b0)*2 + b15. Pooling + init + iter0 fused;
// iter-11 partial moved to k2. Rounds: store, (ld+st)x10, ld.
extern "C" __global__ void __launch_bounds__(NT1) qsim_k1(
    const float* __restrict__ x, const float* __restrict__ kp)
{
    extern __shared__ u64 S[];           // 16384 amps (swizzled)
    __shared__ float tws[16][2];
    __shared__ float ptrig[5][2];
    int tid = threadIdx.x;
    int bi = blockIdx.x;
    int b = bi >> 3, k = (bi >> 2) & 1, bb0 = (bi >> 1) & 1, bb15 = bi & 1;

    if (tid < 16) {
        // fused 7x7 avg pool for cell tid of batch b
        int r = tid >> 2, c = tid & 3;
        const float* px = x + b * 784 + r * 7 * 28 + c * 7;
        float s = 0.f;
#pragma unroll
        for (int u = 0; u < 7; u++)
#pragma unroll
            for (int v = 0; v < 7; v++) s += px[u * 28 + v];
        float ang = s * (1.f / 49.f);
        if (tid == 0) ang += kp[k * 5];      // fold iter-0 RY(p0) on wire 0
        float h = 0.5f * ang;
        tws[tid][0] = cosf(h); tws[tid][1] = sinf(h);
    }
    if (tid < 5) {
        float h = 0.5f * kp[k * 5 + tid];
        ptrig[tid][0] = cosf(h); ptrig[tid][1] = sinf(h);
    }
    __syncthreads();

    float c0 = ptrig[0][0], s0 = ptrig[0][1];
    float c1 = ptrig[1][0], s1 = ptrig[1][1];
    float c2 = ptrig[2][0], s2 = ptrig[2][1];
    float c3 = ptrig[3][0], s3 = ptrig[3][1];
    float c4 = ptrig[4][0], s4 = ptrig[4][1];
    u64 cc0 = pk2(c0, c0), ss0 = pk2(s0, s0), ns0 = pk2(-s0, -s0);
    u64 cc1 = pk2(c1, c1), ss1 = pk2(s1, s1), ns1 = pk2(-s1, -s1);
    u64 cc2 = pk2(c2, c2), ss2 = pk2(s2, s2), ns2 = pk2(-s2, -s2);
    u64 cc3 = pk2(c3, c3), sp3 = pk2(s3, -s3);
    u64 cc4 = pk2(c4, c4), sp4 = pk2(s4, -s4);

    // ---- merged init (product state) + iteration 0 (real until first RX) ----
    {
        float A = tws[0][bb0] * tws[15][bb15];
        float tc[14], ts[14];
#pragma unroll
        for (int w = 1; w <= 14; ++w) { tc[w - 1] = tws[w][0]; ts[w - 1] = tws[w][1]; }
        if (bb0) { float t = tc[2]; tc[2] = ts[2]; ts[2] = t; }   // X on wire 3 when wire0==1
        // per-e group factors: e bit2 -> wire1 (tbl 0), bit1 -> wire3 (tbl 2), bit0 -> wire4 (tbl 3)
        float f[8];
#pragma unroll
        for (int e = 0; e < 8; e++)
            f[e] = ((e & 4) ? ts[0] : tc[0]) * ((e & 2) ? ts[2] : tc[2]) * ((e & 1) ? ts[3] : tc[3]);
        for (int g = tid; g < 2048; g += NT1) {
            int base = (g & 0x3FF) | ((g >> 10) << 12);
            // product over non-group bits: idx bit j (j=0..9) = wire 14-j -> tbl 13-j; idx bit12 = wire2 -> tbl 1
            float P = A;
#pragma unroll
            for (int j = 0; j < 10; j++)
                P *= ((g >> j) & 1) ? ts[13 - j] : tc[13 - j];
            P *= ((g >> 10) & 1) ? ts[1] : tc[1];
            float r[8];
#pragma unroll
            for (int e = 0; e < 8; e++) r[e] = P * f[e];
            // RY(p1) wire3 (e bit1): pairs m in {0,1,4,5}
#pragma unroll
            for (int m = 0; m < 8; m++) {
                if (m & 2) continue;
                float u = r[m], v = r[m | 2];
                r[m] = c1 * u - s1 * v;  r[m | 2] = s1 * u + c1 * v;
            }
            // RY(p2) wire1 (e bit2): pairs m in {0..3}
#pragma unroll
            for (int m = 0; m < 4; m++) {
                float u = r[m], v = r[m | 4];
                r[m] = c2 * u - s2 * v;  r[m | 4] = s2 * u + c2 * v;
            }
            // CNOT(1,4): control bit2, target bit0
            { float t = r[4]; r[4] = r[5]; r[5] = t; }
            { float t = r[6]; r[6] = r[7]; r[7] = t; }
            // CNOT(3,1): control bit1, target bit2
            { float t = r[2]; r[2] = r[6]; r[6] = t; }
            { float t = r[3]; r[3] = r[7]; r[7] = t; }
            // RX(p3) wire4 (bit0): real -> complex
            u64 a[8];
#pragma unroll
            for (int m = 0; m < 8; m += 2) {
                a[m]     = pk2(c3 * r[m],     -s3 * r[m | 1]);
                a[m | 1] = pk2(c3 * r[m | 1], -s3 * r[m]);
            }
            // RX(p4) wire1 (bit2): packed
            rxg<2, 8>(a, cc4, sp4);
#pragma unroll
            for (int e = 0; e < 8; e++)
                S[sphys(base | ((e & 3) << 10) | ((e >> 2) << 13))] = a[e];
        }
    }
    __syncthreads();

    // ---- iterations 1..10 (generic 4-bit group: wires i,i+1,i+3,i+4) ----
#pragma unroll
    for (int i = 1; i <= 10; i++) {
        const int B0 = 10 - i, B2 = 13 - i;
        {
            int g = tid;                 // 1024 groups, 1024 threads
            int low = g & ((1 << B0) - 1);
            int rest = g >> B0;
            int base = low | ((rest & 1) << (B0 + 2)) | ((rest >> 1) << (B0 + 5));
            int off[16]; u64 a[16];
#pragma unroll
            for (int e = 0; e < 16; e++) {
                int idx = base | ((e & 3) << B0) | ((e >> 2) << B2);
                off[e] = sphys(idx); a[e] = S[off[e]];
            }
            ryg<3, 16>(a, cc0, ss0, ns0);   // RY(p0) wire i
            cng<3, 1, 16>(a);               // CNOT(i, i+3)
            ryg<1, 16>(a, cc1, ss1, ns1);   // RY(p1) wire i+3
            ryg<2, 16>(a, cc2, ss2, ns2);   // RY(p2) wire i+1
            cng<2, 0, 16>(a);               // CNOT(i+1, i+4)
            cng<1, 2, 16>(a);               // CNOT(i+3, i+1)
            rxg<0, 16>(a, cc3, sp3);        // RX(p3) wire i+4
            rxg<2, 16>(a, cc4, sp4);        // RX(p4) wire i+1
#pragma unroll
            for (int e = 0; e < 16; e++) S[off[e]] = a[e];
        }
        __syncthreads();
    }

    // ---- spill sub-state (coalesced); iteration 11 handled in k2 ----
    u64* outp = g_state + (size_t)bi * 16384u;
    for (int j = tid; j < 16384; j += NT1) outp[j] = S[sphys(j)];
}

// ---------------- kernel 2: iteration 11 + measurement (5-bit WHT) ----------------
// 128 blocks = 32 statevectors x 4 partial slices; 256 threads.
// Groups of 32 amps over wires 11..15 (e5: bit4=w11, bit3=w12, bit2=w13, bit1=w14, bit0=w15).
extern "C" __global__ void __launch_bounds__(256) qsim_k2(const float* __restrict__ kp) {
    constexpr Masks MK = compute_masks();
    int tid = threadIdx.x;
    int blk = blockIdx.x;
    int bk = blk >> 2, part = blk & 3;
    int b = bk >> 1, k = bk & 1;

    float c0, s0, c1, s1, c2, s2, c3, s3, c4, s4;
    { float h = 0.5f * kp[k * 5 + 0]; c0 = cosf(h); s0 = sinf(h); }
    { float h = 0.5f * kp[k * 5 + 1]; c1 = cosf(h); s1 = sinf(h); }
    { float h = 0.5f * kp[k * 5 + 2]; c2 = cosf(h); s2 = sinf(h); }
    { float h = 0.5f * kp[k * 5 + 3]; c3 = cosf(h); s3 = sinf(h); }
    { float h = 0.5f * kp[k * 5 + 4]; c4 = cosf(h); s4 = sinf(h); }
    u64 cc0 = pk2(c0, c0), ss0 = pk2(s0, s0), ns0 = pk2(-s0, -s0);
    u64 cc1 = pk2(c1, c1), ss1 = pk2(s1, s1), ns1 = pk2(-s1, -s1);
    u64 cc2 = pk2(c2, c2), ss2 = pk2(s2, s2), ns2 = pk2(-s2, -s2);
    u64 cc3 = pk2(c3, c3), sp3 = pk2(s3, -s3);
    u64 cc4 = pk2(c4, c4), sp4 = pk2(s4, -s4);

    const u64* base = g_state + (size_t)bk * 65536u;
    float acc[12];
#pragma unroll
    for (int w = 0; w < 12; w++) acc[w] = 0.f;

    // 2048 groups per statevector: gi = b0(bit10) | idx14_hi(10 bits)
    for (int gi = part * 512 + tid; gi < (part + 1) * 512; gi += 256) {
        int b0 = gi >> 10, hi = gi & 1023;
        const u64* p = base + b0 * 32768 + hi * 16;
        u64 a[32];
#pragma unroll
        for (int o = 0; o < 16; o++) {       // o bits 3..0 = wires 11,12,13,14
            a[(o << 1)]     = p[o];          // b15 (wire15) = 0
            a[(o << 1) | 1] = p[o + 16384];  // wire15 = 1
        }
        // iteration 11 (full):
        ryg<4, 32>(a, cc0, ss0, ns0);   // RY(p0) wire 11
        cng<4, 1, 32>(a);               // CNOT(11,14)
        ryg<1, 32>(a, cc1, ss1, ns1);   // RY(p1) wire 14
        ryg<3, 32>(a, cc2, ss2, ns2);   // RY(p2) wire 12
        cng<3, 0, 32>(a);               // CNOT(12,15)
        cng<1, 3, 32>(a);               // CNOT(14,12)
        rxg<0, 32>(a, cc3, sp3);        // RX(p3) wire 15
        rxg<3, 32>(a, cc4, sp4);        // RX(p4) wire 12
        float pr[32];
#pragma unroll
        for (int e = 0; e < 32; e++) {
            float xr, xi; upk(a[e], xr, xi);
            pr[e] = xr * xr + xi * xi;
        }
        // 5-bit Walsh-Hadamard: pr[m] <- sum_e (-1)^{popc(m&e)} pr[e]
#pragma unroll
        for (int bit = 1; bit < 32; bit <<= 1) {
#pragma unroll
            for (int m = 0; m < 32; m++) {
                if (m & bit) continue;
                float u = pr[m], v = pr[m | bit];
                pr[m] = u + v; pr[m | bit] = u - v;
            }
        }
        int base14 = hi << 4;
#pragma unroll
        for (int w = 0; w < 12; w++) {
            float s = pr[MK.inner[w]];
            int par = (__popc(base14 & MK.outer14[w]) + (b0 & MK.w0f[w])) & 1;
            acc[w] += par ? -s : s;
        }
    }
    // deterministic reduction (8 warps)
#pragma unroll
    for (int w = 0; w < 12; w++)
        for (int o = 16; o > 0; o >>= 1)
            acc[w] += __shfl_xor_sync(0xffffffffu, acc[w], o);
    __shared__ float part_s[8][12];
    int wid = tid >> 5, lane = tid & 31;
    if (lane == 0) {
#pragma unroll
        for (int w = 0; w < 12; w++) part_s[wid][w] = acc[w];
    }
    __syncthreads();
    if (tid < 12) {
        float s = 0.f;
#pragma unroll
        for (int r = 0; r < 8; r++) s += part_s[r][tid];
        g_featsP[part * 384 + b * 24 + k * 12 + tid] = s;
    }
}

// ---------------- kernel 3: tiny MLP 24->128->64->4 ----------------
// 16 blocks (one per batch item), 256 threads. Weights staged via float4
// global loads; padded smem strides (25 / 129) keep LDS conflict-free.
#define K3_SMEM_FLOATS 12380
extern "C" __global__ void __launch_bounds__(256) qsim_k3(
    const float* __restrict__ w1, const float* __restrict__ bb1,
    const float* __restrict__ w2, const float* __restrict__ bb2,
    const float* __restrict__ w3, const float* __restrict__ bb3,
    float* __restrict__ out)
{
    extern __shared__ float sm[];
    float* w1s = sm;             // 128 x stride 25  (3200)
    float* w2s = sm + 3200;      // 64 x stride 129  (8256)
    float* w3s = sm + 11456;     // 256
    float* b1s = sm + 11712;     // 128
    float* b2s = sm + 11840;     // 64
    float* b3s = sm + 11904;     // 4
    float* fts = sm + 11908;     // 24
    float* h1  = sm + 11936;     // 128
    float* h2  = sm + 12064;     // 64
    float* prt = sm + 12124;     // 256

    int tid = threadIdx.x;
    int b = blockIdx.x;

    // ---- stage weights (float4 global reads, scalar padded STS) ----
    const float4* w1v = (const float4*)w1;
    for (int t = tid; t < 768; t += 256) {
        float4 v = w1v[t];
        int base = 4 * t, row = base / 24, col = base % 24;
        float* d = w1s + row * 25 + col;
        d[0] = v.x; d[1] = v.y; d[2] = v.z; d[3] = v.w;
    }
    const float4* w2v = (const float4*)w2;
    for (int t = tid; t < 2048; t += 256) {
        float4 v = w2v[t];
        int base = 4 * t, row = base >> 7, col = base & 127;
        float* d = w2s + row * 129 + col;
        d[0] = v.x; d[1] = v.y; d[2] = v.z; d[3] = v.w;
    }
    if (tid < 64) {
        float4 v = ((const float4*)w3)[tid];
        float* d = w3s + 4 * tid;
        d[0] = v.x; d[1] = v.y; d[2] = v.z; d[3] = v.w;
    }
    if (tid < 128) b1s[tid] = bb1[tid];
    if (tid < 64)  b2s[tid] = bb2[tid];
    if (tid < 4)   b3s[tid] = bb3[tid];
    if (tid < 24) {
        float s = g_featsP[b * 24 + tid] + g_featsP[384 + b * 24 + tid]
                + g_featsP[768 + b * 24 + tid] + g_featsP[1152 + b * 24 + tid];
        fts[tid] = s;
    }
    __syncthreads();

    // ---- fc1: one output unit per thread (threads 0..127) ----
    if (tid < 128) {
        float s = b1s[tid];
        const float* wr = w1s + tid * 25;
#pragma unroll
        for (int i = 0; i < 24; i++) s += wr[i] * fts[i];
        h1[tid] = fmaxf(s, 0.f);
    }
    __syncthreads();

    // ---- fc2: 64 units, 4 threads per unit (split the 128-dot into 32s) ----
    {
        int j = tid & 63, h = tid >> 6;
        const float* wr = w2s + j * 129 + h * 32;
        const float* hr = h1 + h * 32;
        float s = 0.f;
#pragma unroll
        for (int i = 0; i < 32; i++) s += wr[i] * hr[i];
        prt[tid] = s;
    }
    __syncthreads();
    if (tid < 64)
        h2[tid] = fmaxf(b2s[tid] + prt[tid] + prt[tid + 64] + prt[tid + 128] + prt[tid + 192], 0.f);
    __syncthreads();

    // ---- fc3: one output per warp (threads 0..127), warp-shuffle reduce ----
    if (tid < 128) {
        int o = tid >> 5, l = tid & 31;
        float s = w3s[o * 64 + l] * h2[l] + w3s[o * 64 + 32 + l] * h2[32 + l];
#pragma unroll
        for (int d = 16; d > 0; d >>= 1) s += __shfl_xor_sync(0xffffffffu, s, d);
        if (l == 0) out[b * 4 + o] = s + b3s[o];
    }
}

// ---------------- host launcher ----------------
extern "C" void kernel_launch(void* const* d_in, const int* in_sizes, int n_in,
                              void* d_out, int out_size)
{
    const float* x  = (const float*)d_in[0];
    const float* kp = (const float*)d_in[1];
    const float* w1 = (const float*)d_in[2];
    const float* b1 = (const float*)d_in[3];
    const float* w2 = (const float*)d_in[4];
    const float* b2 = (const float*)d_in[5];
    const float* w3 = (const float*)d_in[6];
    const float* b3 = (const float*)d_in[7];
    float* out = (float*)d_out;

    cudaFuncSetAttribute(qsim_k1, cudaFuncAttributeMaxDynamicSharedMemorySize, 131072);
    cudaFuncSetAttribute(qsim_k3, cudaFuncAttributeMaxDynamicSharedMemorySize,
                         K3_SMEM_FLOATS * (int)sizeof(float));

    qsim_k1<<<128, NT1, 131072>>>(x, kp);
    qsim_k2<<<128, 256>>>(kp);
    qsim_k3<<<16, 256, K3_SMEM_FLOATS * (int)sizeof(float)>>>(w1, b1, w2, b2, w3, b3, out);
}

// round 14
// speedup vs baseline: 1.4287x; 1.4287x over previous
#include <cuda_runtime.h>
#include <math.h>

#define NT1 1024

typedef unsigned long long u64;

// Scratch (static device arrays — no allocation)
__device__ u64   g_state[32u * 65536u];   // 16 MB: [b][k][b0][b15][idx14], packed (re,im)
__device__ float g_featsP[4 * 16 * 24];   // partial quantum features [part][b][24]

// ---------------- f32x2 packed helpers (sm_103a) ----------------
__device__ __forceinline__ u64 pk2(float x, float y) {
    u64 r; asm("mov.b64 %0, {%1,%2};" : "=l"(r) : "f"(x), "f"(y)); return r;
}
__device__ __forceinline__ u64 f2mul(u64 a, u64 b) {
    u64 d; asm("mul.rn.f32x2 %0, %1, %2;" : "=l"(d) : "l"(a), "l"(b)); return d;
}
__device__ __forceinline__ u64 f2fma(u64 a, u64 b, u64 c) {
    u64 d; asm("fma.rn.f32x2 %0, %1, %2, %3;" : "=l"(d) : "l"(a), "l"(b), "l"(c)); return d;
}
__device__ __forceinline__ u64 f2swap(u64 a) {
    unsigned lo, hi; asm("mov.b64 {%0,%1}, %2;" : "=r"(lo), "=r"(hi) : "l"(a));
    u64 d; asm("mov.b64 %0, {%1,%2};" : "=l"(d) : "r"(hi), "r"(lo)); return d;
}
__device__ __forceinline__ void upk(u64 a, float& x, float& y) {
    asm("mov.b64 {%0,%1}, %2;" : "=f"(x), "=f"(y) : "l"(a));
}

// Swizzle chosen so the bank map (phys & 15) is injective on every
// iteration's 4-bit lane subspace (verified for all rounds' lane bit-sets):
// contribution of idx bits to bank bits: 0->b0, 1->b1, 2->b2, 3->b3,
// 4->b2, 5->b3, 6->b0+b2, 7->b1+b3.
__device__ __forceinline__ int sphys(int idx) {
    return idx ^ ((idx >> 2) & 12) ^ (5 * ((idx >> 6) & 3));
}

// RY on packed pair: u' = c*u - s*v ; v' = s*u + c*v (elementwise on re/im)
template<int T, int N>
__device__ __forceinline__ void ryg(u64* a, u64 cc, u64 ss, u64 nss) {
#pragma unroll
    for (int m = 0; m < N; m++) {
        if (m & (1 << T)) continue;
        int v = m | (1 << T);
        u64 au = a[m], av = a[v];
        a[m] = f2fma(cc, au, f2mul(nss, av));
        a[v] = f2fma(cc, av, f2mul(ss, au));
    }
}
// RX: u' = c*u + (s,-s)*swap(v) ; v' = c*v + (s,-s)*swap(u)
template<int T, int N>
__device__ __forceinline__ void rxg(u64* a, u64 cc, u64 sp) {
#pragma unroll
    for (int m = 0; m < N; m++) {
        if (m & (1 << T)) continue;
        int v = m | (1 << T);
        u64 au = a[m], av = a[v];
        a[m] = f2fma(cc, au, f2mul(sp, f2swap(av)));
        a[v] = f2fma(cc, av, f2mul(sp, f2swap(au)));
    }
}
template<int C, int T, int N>
__device__ __forceinline__ void cng(u64* a) {
#pragma unroll
    for (int m = 0; m < N; m++) {
        if (!(m & (1 << C)) || (m & (1 << T))) continue;
        int v = m | (1 << T);
        u64 t = a[m]; a[m] = a[v]; a[v] = t;
    }
}

// ---------------- compile-time parity masks for the 36-CNOT cascade ----------------
// inner: e5 bits (bit4=wire11 .. bit0=wire15); outer: idx14 bits 13..4 (wires 1..10)
struct Masks { unsigned inner[12]; unsigned outer14[12]; unsigned w0f[12]; };
__host__ __device__ constexpr Masks compute_masks() {
    Masks M{};
    int cs[36] = {}, ts2[36] = {}; int n = 0;
    for (int i = 0; i < 12; i++) {
        cs[n] = i + 1; ts2[n] = i; n++;
        cs[n] = i + 3; ts2[n] = i; n++;
        cs[n] = i + 4; ts2[n] = i; n++;
    }
    for (int w = 0; w < 12; w++) {
        unsigned m = 1u << w;
        for (int j = 35; j >= 0; --j)
            if ((m >> ts2[j]) & 1u) m ^= 1u << cs[j];
        unsigned inner = 0, outer = 0;
        M.w0f[w] = m & 1u;
        for (int ww = 1; ww <= 10; ++ww)
            if ((m >> ww) & 1u) outer |= 1u << (14 - ww);
        for (int ww = 11; ww <= 15; ++ww)
            if ((m >> ww) & 1u) inner |= 1u << (15 - ww);
        M.inner[w] = inner; M.outer14[w] = outer;
    }
    return M;
}

// ---------------- kernel 1: 14-qubit smem-resident simulation ----------------
// 128 blocks: bi = ((b*2 + k)*2 + b0)*2 + b15. Pooling folded into prologue.
// R6 structure (separate init / iter0 rounds — low register pressure) with
// the conflict-free swizzle; iteration 11 moved to k2.
extern "C" __global__ void __launch_bounds__(NT1) qsim_k1(
    const float* __restrict__ x, const float* __restrict__ kp)
{
    extern __shared__ u64 S[];           // 16384 amps (swizzled)
    __shared__ float tws[16][2];
    __shared__ float ptrig[5][2];
    int tid = threadIdx.x;
    int bi = blockIdx.x;
    int b = bi >> 3, k = (bi >> 2) & 1, bb0 = (bi >> 1) & 1, bb15 = bi & 1;

    if (tid < 16) {
        // fused 7x7 avg pool for cell tid of batch b
        int r = tid >> 2, c = tid & 3;
        const float* px = x + b * 784 + r * 7 * 28 + c * 7;
        float s = 0.f;
#pragma unroll
        for (int u = 0; u < 7; u++)
#pragma unroll
            for (int v = 0; v < 7; v++) s += px[u * 28 + v];
        float ang = s * (1.f / 49.f);
        if (tid == 0) ang += kp[k * 5];      // fold iter-0 RY(p0) on wire 0
        float h = 0.5f * ang;
        tws[tid][0] = cosf(h); tws[tid][1] = sinf(h);
    }
    if (tid < 5) {
        float h = 0.5f * kp[k * 5 + tid];
        ptrig[tid][0] = cosf(h); ptrig[tid][1] = sinf(h);
    }
    __syncthreads();

    float c0 = ptrig[0][0], s0 = ptrig[0][1];
    float c1 = ptrig[1][0], s1 = ptrig[1][1];
    float c2 = ptrig[2][0], s2 = ptrig[2][1];
    float c3 = ptrig[3][0], s3 = ptrig[3][1];
    float c4 = ptrig[4][0], s4 = ptrig[4][1];
    u64 cc0 = pk2(c0, c0), ss0 = pk2(s0, s0), ns0 = pk2(-s0, -s0);
    u64 cc1 = pk2(c1, c1), ss1 = pk2(s1, s1), ns1 = pk2(-s1, -s1);
    u64 cc2 = pk2(c2, c2), ss2 = pk2(s2, s2), ns2 = pk2(-s2, -s2);
    u64 cc3 = pk2(c3, c3), sp3 = pk2(s3, -s3);
    u64 cc4 = pk2(c4, c4), sp4 = pk2(s4, -s4);

    // ---- init: product state (encoder folded; CNOT(0,3) folded as table swap) ----
    {
        float A = tws[0][bb0] * tws[15][bb15];
        float tc[14], ts[14];
#pragma unroll
        for (int w = 1; w <= 14; ++w) { tc[w - 1] = tws[w][0]; ts[w - 1] = tws[w][1]; }
        if (bb0) { float t = tc[2]; tc[2] = ts[2]; ts[2] = t; }   // X on wire 3 when wire0==1
        for (int j = tid; j < 16384; j += NT1) {
            float p = A;
#pragma unroll
            for (int w = 1; w <= 14; ++w)
                p *= ((j >> (14 - w)) & 1) ? ts[w - 1] : tc[w - 1];
            S[sphys(j)] = pk2(p, 0.f);
        }
    }
    __syncthreads();

    // ---- iteration 0 (wires 1,3,4 local; wire-0 ops folded) ----
    for (int g = tid; g < 2048; g += NT1) {
        // mask bits {13,11,10}; non-mask: bits 0..9 and bit 12
        int base = (g & 0x3FF) | ((g >> 10) << 12);
        int off[8]; u64 a[8];
#pragma unroll
        for (int e = 0; e < 8; e++) {
            int idx = base | ((e & 3) << 10) | ((e >> 2) << 13);
            off[e] = sphys(idx); a[e] = S[off[e]];
        }
        ryg<1, 8>(a, cc1, ss1, ns1);  // RY(p1) wire 3
        ryg<2, 8>(a, cc2, ss2, ns2);  // RY(p2) wire 1
        cng<2, 0, 8>(a);              // CNOT(1,4)
        cng<1, 2, 8>(a);              // CNOT(3,1)
        rxg<0, 8>(a, cc3, sp3);       // RX(p3) wire 4
        rxg<2, 8>(a, cc4, sp4);       // RX(p4) wire 1
#pragma unroll
        for (int e = 0; e < 8; e++) S[off[e]] = a[e];
    }
    __syncthreads();

    // ---- iterations 1..10 (generic 4-bit group: wires i,i+1,i+3,i+4) ----
    // FULLY UNROLLED: all masks/shifts become compile-time constants.
#pragma unroll
    for (int i = 1; i <= 10; i++) {
        const int B0 = 10 - i, B2 = 13 - i;
        {
            int g = tid;                 // 1024 groups, 1024 threads
            int low = g & ((1 << B0) - 1);
            int rest = g >> B0;
            int base = low | ((rest & 1) << (B0 + 2)) | ((rest >> 1) << (B0 + 5));
            int off[16]; u64 a[16];
#pragma unroll
            for (int e = 0; e < 16; e++) {
                int idx = base | ((e & 3) << B0) | ((e >> 2) << B2);
                off[e] = sphys(idx); a[e] = S[off[e]];
            }
            ryg<3, 16>(a, cc0, ss0, ns0);   // RY(p0) wire i
            cng<3, 1, 16>(a);               // CNOT(i, i+3)
            ryg<1, 16>(a, cc1, ss1, ns1);   // RY(p1) wire i+3
            ryg<2, 16>(a, cc2, ss2, ns2);   // RY(p2) wire i+1
            cng<2, 0, 16>(a);               // CNOT(i+1, i+4)
            cng<1, 2, 16>(a);               // CNOT(i+3, i+1)
            rxg<0, 16>(a, cc3, sp3);        // RX(p3) wire i+4
            rxg<2, 16>(a, cc4, sp4);        // RX(p4) wire i+1
#pragma unroll
            for (int e = 0; e < 16; e++) S[off[e]] = a[e];
        }
        __syncthreads();
    }

    // ---- spill sub-state (coalesced); iteration 11 handled in k2 ----
    u64* outp = g_state + (size_t)bi * 16384u;
    for (int j = tid; j < 16384; j += NT1) outp[j] = S[sphys(j)];
}

// ---------------- kernel 2: iteration 11 + measurement (5-bit WHT) ----------------
// 128 blocks = 32 statevectors x 4 partial slices; 256 threads.
// Groups of 32 amps over wires 11..15 (e5: bit4=w11, bit3=w12, bit2=w13, bit1=w14, bit0=w15).
extern "C" __global__ void __launch_bounds__(256) qsim_k2(const float* __restrict__ kp) {
    constexpr Masks MK = compute_masks();
    int tid = threadIdx.x;
    int blk = blockIdx.x;
    int bk = blk >> 2, part = blk & 3;
    int b = bk >> 1, k = bk & 1;

    float c0, s0, c1, s1, c2, s2, c3, s3, c4, s4;
    { float h = 0.5f * kp[k * 5 + 0]; c0 = cosf(h); s0 = sinf(h); }
    { float h = 0.5f * kp[k * 5 + 1]; c1 = cosf(h); s1 = sinf(h); }
    { float h = 0.5f * kp[k * 5 + 2]; c2 = cosf(h); s2 = sinf(h); }
    { float h = 0.5f * kp[k * 5 + 3]; c3 = cosf(h); s3 = sinf(h); }
    { float h = 0.5f * kp[k * 5 + 4]; c4 = cosf(h); s4 = sinf(h); }
    u64 cc0 = pk2(c0, c0), ss0 = pk2(s0, s0), ns0 = pk2(-s0, -s0);
    u64 cc1 = pk2(c1, c1), ss1 = pk2(s1, s1), ns1 = pk2(-s1, -s1);
    u64 cc2 = pk2(c2, c2), ss2 = pk2(s2, s2), ns2 = pk2(-s2, -s2);
    u64 cc3 = pk2(c3, c3), sp3 = pk2(s3, -s3);
    u64 cc4 = pk2(c4, c4), sp4 = pk2(s4, -s4);

    const u64* base = g_state + (size_t)bk * 65536u;
    float acc[12];
#pragma unroll
    for (int w = 0; w < 12; w++) acc[w] = 0.f;

    // 2048 groups per statevector: gi = b0(bit10) | idx14_hi(10 bits)
    for (int gi = part * 512 + tid; gi < (part + 1) * 512; gi += 256) {
        int b0 = gi >> 10, hi = gi & 1023;
        const u64* p = base + b0 * 32768 + hi * 16;
        u64 a[32];
#pragma unroll
        for (int o = 0; o < 16; o++) {       // o bits 3..0 = wires 11,12,13,14
            a[(o << 1)]     = p[o];          // b15 (wire15) = 0
            a[(o << 1) | 1] = p[o + 16384];  // wire15 = 1
        }
        // iteration 11 (full):
        ryg<4, 32>(a, cc0, ss0, ns0);   // RY(p0) wire 11
        cng<4, 1, 32>(a);               // CNOT(11,14)
        ryg<1, 32>(a, cc1, ss1, ns1);   // RY(p1) wire 14
        ryg<3, 32>(a, cc2, ss2, ns2);   // RY(p2) wire 12
        cng<3, 0, 32>(a);               // CNOT(12,15)
        cng<1, 3, 32>(a);               // CNOT(14,12)
        rxg<0, 32>(a, cc3, sp3);        // RX(p3) wire 15
        rxg<3, 32>(a, cc4, sp4);        // RX(p4) wire 12
        float pr[32];
#pragma unroll
        for (int e = 0; e < 32; e++) {
            float xr, xi; upk(a[e], xr, xi);
            pr[e] = xr * xr + xi * xi;
        }
        // 5-bit Walsh-Hadamard: pr[m] <- sum_e (-1)^{popc(m&e)} pr[e]
#pragma unroll
        for (int bit = 1; bit < 32; bit <<= 1) {
#pragma unroll
            for (int m = 0; m < 32; m++) {
                if (m & bit) continue;
                float u = pr[m], v = pr[m | bit];
                pr[m] = u + v; pr[m | bit] = u - v;
            }
        }
        int base14 = hi << 4;
#pragma unroll
        for (int w = 0; w < 12; w++) {
            float s = pr[MK.inner[w]];
            int par = (__popc(base14 & MK.outer14[w]) + (b0 & MK.w0f[w])) & 1;
            acc[w] += par ? -s : s;
        }
    }
    // deterministic reduction (8 warps)
#pragma unroll
    for (int w = 0; w < 12; w++)
        for (int o = 16; o > 0; o >>= 1)
            acc[w] += __shfl_xor_sync(0xffffffffu, acc[w], o);
    __shared__ float part_s[8][12];
    int wid = tid >> 5, lane = tid & 31;
    if (lane == 0) {
#pragma unroll
        for (int w = 0; w < 12; w++) part_s[wid][w] = acc[w];
    }
    __syncthreads();
    if (tid < 12) {
        float s = 0.f;
#pragma unroll
        for (int r = 0; r < 8; r++) s += part_s[r][tid];
        g_featsP[part * 384 + b * 24 + k * 12 + tid] = s;
    }
}

// ---------------- kernel 3: tiny MLP 24->128->64->4 ----------------
// 16 blocks (one per batch item), 256 threads. Weights staged via float4
// global loads; padded smem strides (25 / 129) keep LDS conflict-free.
#define K3_SMEM_FLOATS 12380
extern "C" __global__ void __launch_bounds__(256) qsim_k3(
    const float* __restrict__ w1, const float* __restrict__ bb1,
    const float* __restrict__ w2, const float* __restrict__ bb2,
    const float* __restrict__ w3, const float* __restrict__ bb3,
    float* __restrict__ out)
{
    extern __shared__ float sm[];
    float* w1s = sm;             // 128 x stride 25  (3200)
    float* w2s = sm + 3200;      // 64 x stride 129  (8256)
    float* w3s = sm + 11456;     // 256
    float* b1s = sm + 11712;     // 128
    float* b2s = sm + 11840;     // 64
    float* b3s = sm + 11904;     // 4
    float* fts = sm + 11908;     // 24
    float* h1  = sm + 11936;     // 128
    float* h2  = sm + 12064;     // 64
    float* prt = sm + 12124;     // 256

    int tid = threadIdx.x;
    int b = blockIdx.x;

    // ---- stage weights (float4 global reads, scalar padded STS) ----
    const float4* w1v = (const float4*)w1;
    for (int t = tid; t < 768; t += 256) {
        float4 v = w1v[t];
        int base = 4 * t, row = base / 24, col = base % 24;
        float* d = w1s + row * 25 + col;
        d[0] = v.x; d[1] = v.y; d[2] = v.z; d[3] = v.w;
    }
    const float4* w2v = (const float4*)w2;
    for (int t = tid; t < 2048; t += 256) {
        float4 v = w2v[t];
        int base = 4 * t, row = base >> 7, col = base & 127;
        float* d = w2s + row * 129 + col;
        d[0] = v.x; d[1] = v.y; d[2] = v.z; d[3] = v.w;
    }
    if (tid < 64) {
        float4 v = ((const float4*)w3)[tid];
        float* d = w3s + 4 * tid;
        d[0] = v.x; d[1] = v.y; d[2] = v.z; d[3] = v.w;
    }
    if (tid < 128) b1s[tid] = bb1[tid];
    if (tid < 64)  b2s[tid] = bb2[tid];
    if (tid < 4)   b3s[tid] = bb3[tid];
    if (tid < 24) {
        float s = g_featsP[b * 24 + tid] + g_featsP[384 + b * 24 + tid]
                + g_featsP[768 + b * 24 + tid] + g_featsP[1152 + b * 24 + tid];
        fts[tid] = s;
    }
    __syncthreads();

    // ---- fc1: one output unit per thread (threads 0..127) ----
    if (tid < 128) {
        float s = b1s[tid];
        const float* wr = w1s + tid * 25;
#pragma unroll
        for (int i = 0; i < 24; i++) s += wr[i] * fts[i];
        h1[tid] = fmaxf(s, 0.f);
    }
    __syncthreads();

    // ---- fc2: 64 units, 4 threads per unit (split the 128-dot into 32s) ----
    {
        int j = tid & 63, h = tid >> 6;
        const float* wr = w2s + j * 129 + h * 32;
        const float* hr = h1 + h * 32;
        float s = 0.f;
#pragma unroll
        for (int i = 0; i < 32; i++) s += wr[i] * hr[i];
        prt[tid] = s;
    }
    __syncthreads();
    if (tid < 64)
        h2[tid] = fmaxf(b2s[tid] + prt[tid] + prt[tid + 64] + prt[tid + 128] + prt[tid + 192], 0.f);
    __syncthreads();

    // ---- fc3: one output per warp (threads 0..127), warp-shuffle reduce ----
    if (tid < 128) {
        int o = tid >> 5, l = tid & 31;
        float s = w3s[o * 64 + l] * h2[l] + w3s[o * 64 + 32 + l] * h2[32 + l];
#pragma unroll
        for (int d = 16; d > 0; d >>= 1) s += __shfl_xor_sync(0xffffffffu, s, d);
        if (l == 0) out[b * 4 + o] = s + b3s[o];
    }
}

// ---------------- host launcher ----------------
extern "C" void kernel_launch(void* const* d_in, const int* in_sizes, int n_in,
                              void* d_out, int out_size)
{
    const float* x  = (const float*)d_in[0];
    const float* kp = (const float*)d_in[1];
    const float* w1 = (const float*)d_in[2];
    const float* b1 = (const float*)d_in[3];
    const float* w2 = (const float*)d_in[4];
    const float* b2 = (const float*)d_in[5];
    const float* w3 = (const float*)d_in[6];
    const float* b3 = (const float*)d_in[7];
    float* out = (float*)d_out;

    cudaFuncSetAttribute(qsim_k1, cudaFuncAttributeMaxDynamicSharedMemorySize, 131072);
    cudaFuncSetAttribute(qsim_k3, cudaFuncAttributeMaxDynamicSharedMemorySize,
                         K3_SMEM_FLOATS * (int)sizeof(float));

    qsim_k1<<<128, NT1, 131072>>>(x, kp);
    qsim_k2<<<128, 256>>>(kp);
    qsim_k3<<<16, 256, K3_SMEM_FLOATS * (int)sizeof(float)>>>(w1, b1, w2, b2, w3, b3, out);
}